// round 2
// baseline (speedup 1.0000x reference)
#include <cuda_runtime.h>
#include <cuda_bf16.h>

#define NN 100000
#define NE 1600000
#define NG 512
#define HID 64
#define NCLS 100
#define IDOFF 1500

// ---------------- device scratch (no allocations allowed) ----------------
__device__ float g_h[NN * HID];        // layer input h
__device__ float g_x[NN * HID];        // (1+eps)*h + agg  (MLP input)
__device__ float g_y[NN * HID];        // MLP output (pre-BN)
__device__ float g_stats[3 * 2 * HID]; // per layer: sum[64], sumsq[64]
__device__ float g_pooled[NG * 3 * HID];

// ---------------- helpers ----------------
__device__ __forceinline__ unsigned f2tf(float f) {
    unsigned u;
    asm("cvt.rna.tf32.f32 %0, %1;" : "=r"(u) : "f"(f));
    return u;
}

__device__ __forceinline__ void mma8(float c[4], unsigned a0, unsigned a1,
                                     unsigned a2, unsigned a3,
                                     unsigned b0, unsigned b1) {
    asm volatile(
        "mma.sync.aligned.m16n8k8.row.col.f32.tf32.tf32.f32 "
        "{%0,%1,%2,%3}, {%4,%5,%6,%7}, {%8,%9}, {%0,%1,%2,%3};\n"
        : "+f"(c[0]), "+f"(c[1]), "+f"(c[2]), "+f"(c[3])
        : "r"(a0), "r"(a1), "r"(a2), "r"(a3), "r"(b0), "r"(b1));
}

// ---------------- kernels ----------------

// zero pooled + stats
__global__ void k_zero() {
    int t = blockIdx.x * blockDim.x + threadIdx.x;
    int stride = gridDim.x * blockDim.x;
    for (int i = t; i < NG * 3 * HID; i += stride) g_pooled[i] = 0.f;
    for (int i = t; i < 3 * 2 * HID; i += stride) g_stats[i] = 0.f;
}

// h = emb[node_ids + IDOFF]
__global__ void k_gather(const int* __restrict__ ids,
                         const float* __restrict__ emb) {
    int t = blockIdx.x * blockDim.x + threadIdx.x;
    if (t >= NN * 16) return;
    int row = t >> 4, q = t & 15;
    int id = ids[row] + IDOFF;
    float4 v = *(const float4*)(emb + (size_t)id * HID + q * 4);
    *(float4*)(g_h + (size_t)row * HID + q * 4) = v;
}

// x = (1+eps[l]) * h
__global__ void k_init(const float* __restrict__ eps, int l) {
    int t = blockIdx.x * blockDim.x + threadIdx.x;
    if (t >= NN * 16) return;
    float s = 1.0f + __ldg(&eps[l]);
    float4 v = *(const float4*)(g_h + (size_t)t * 4);
    v.x *= s; v.y *= s; v.z *= s; v.w *= s;
    *(float4*)(g_x + (size_t)t * 4) = v;
}

// x[dst] += h[src]  (16 lanes / edge, float4 vector RED)
__global__ void k_edge(const int* __restrict__ src,
                       const int* __restrict__ dst) {
    int t = blockIdx.x * blockDim.x + threadIdx.x;
    if (t >= NE * 16) return;
    int e = t >> 4, q = t & 15;
    int s = __ldg(&src[e]);
    int d = __ldg(&dst[e]);
    float4 v = *(const float4*)(g_h + (size_t)s * HID + q * 4);
    float* p = g_x + (size_t)d * HID + q * 4;
    asm volatile("red.global.add.v4.f32 [%0], {%1,%2,%3,%4};"
                 :: "l"(p), "f"(v.x), "f"(v.y), "f"(v.z), "f"(v.w)
                 : "memory");
}

// Fused 3x (Linear 64x64 + ReLU) per GIN layer, 3xTF32 split mma, + BN stats.
// X tiles kept in fp32 in smem (hi/lo split done in registers at A-frag load);
// W pre-split into Whi/Wlo smem tiles.
#define MROWS 128
#define XS 76   // smem row stride for X tiles (conflict-free A-frag loads)
#define WSTR 72 // smem row stride for W tiles (conflict-free B-frag loads)
#define MLP_SMEM ((2 * MROWS * XS + 2 * HID * WSTR + HID + 2 * HID) * 4)

__global__ __launch_bounds__(256)
void k_mlp(const float* __restrict__ Wall, const float* __restrict__ ball, int l) {
    extern __shared__ float sm[];
    float* Xbuf0 = sm;                          // fp32 activations
    float* Xbuf1 = sm + MROWS * XS;
    unsigned* Whi = (unsigned*)(sm + 2 * MROWS * XS);
    unsigned* Wlo = Whi + HID * WSTR;
    float* Bsm = (float*)(Wlo + HID * WSTR);
    float* bstat = Bsm + HID;

    const int t = threadIdx.x;
    const int warp = t >> 5, lane = t & 31;
    const int g = lane >> 2, tg = lane & 3;
    const int row0 = blockIdx.x * MROWS;
    const int wrow = warp * 16;

    if (t < 2 * HID) bstat[t] = 0.f;

    // load X tile (fp32)
    for (int i = t; i < MROWS * 16; i += 256) {
        int r = i >> 4, q = i & 15;
        float4 v = make_float4(0.f, 0.f, 0.f, 0.f);
        int gr = row0 + r;
        if (gr < NN) v = *(const float4*)(g_x + (size_t)gr * HID + q * 4);
        float* p = Xbuf0 + r * XS + q * 4;
        p[0] = v.x; p[1] = v.y; p[2] = v.z; p[3] = v.w;
    }

    float* cur = Xbuf0;
    float* nxt = Xbuf1;

    for (int m = 0; m < 3; m++) {
        __syncthreads();
        const float* W = Wall + (size_t)(l * 3 + m) * HID * HID;
        for (int i = t; i < HID * 16; i += 256) {
            int k = i >> 4, q = i & 15;
            float4 w = *(const float4*)(W + (size_t)k * HID + q * 4);
            unsigned h0 = f2tf(w.x), h1 = f2tf(w.y), h2 = f2tf(w.z), h3 = f2tf(w.w);
            unsigned* ph = Whi + k * WSTR + q * 4;
            ph[0] = h0; ph[1] = h1; ph[2] = h2; ph[3] = h3;
            unsigned* pl = Wlo + k * WSTR + q * 4;
            pl[0] = f2tf(w.x - __uint_as_float(h0));
            pl[1] = f2tf(w.y - __uint_as_float(h1));
            pl[2] = f2tf(w.z - __uint_as_float(h2));
            pl[3] = f2tf(w.w - __uint_as_float(h3));
        }
        if (t < HID) Bsm[t] = ball[(l * 3 + m) * HID + t];
        __syncthreads();

        float acc[8][4];
        #pragma unroll
        for (int n = 0; n < 8; n++) {
            acc[n][0] = 0.f; acc[n][1] = 0.f; acc[n][2] = 0.f; acc[n][3] = 0.f;
        }

        #pragma unroll
        for (int k0 = 0; k0 < 8; k0++) {
            int kk = k0 * 8;
            float a0f = cur[(wrow + g) * XS + kk + tg];
            float a1f = cur[(wrow + g + 8) * XS + kk + tg];
            float a2f = cur[(wrow + g) * XS + kk + tg + 4];
            float a3f = cur[(wrow + g + 8) * XS + kk + tg + 4];
            unsigned a0h = f2tf(a0f), a1h = f2tf(a1f);
            unsigned a2h = f2tf(a2f), a3h = f2tf(a3f);
            unsigned a0l = f2tf(a0f - __uint_as_float(a0h));
            unsigned a1l = f2tf(a1f - __uint_as_float(a1h));
            unsigned a2l = f2tf(a2f - __uint_as_float(a2h));
            unsigned a3l = f2tf(a3f - __uint_as_float(a3h));
            #pragma unroll
            for (int n = 0; n < 8; n++) {
                unsigned b0h = Whi[(kk + tg) * WSTR + n * 8 + g];
                unsigned b1h = Whi[(kk + tg + 4) * WSTR + n * 8 + g];
                unsigned b0l = Wlo[(kk + tg) * WSTR + n * 8 + g];
                unsigned b1l = Wlo[(kk + tg + 4) * WSTR + n * 8 + g];
                mma8(acc[n], a0h, a1h, a2h, a3h, b0l, b1l);
                mma8(acc[n], a0l, a1l, a2l, a3l, b0h, b1h);
                mma8(acc[n], a0h, a1h, a2h, a3h, b0h, b1h);
            }
        }

        if (m < 2) {
            #pragma unroll
            for (int n = 0; n < 8; n++) {
                int c = n * 8 + 2 * tg;
                float b0f = Bsm[c], b1f = Bsm[c + 1];
                float d0 = fmaxf(acc[n][0] + b0f, 0.f);
                float d1 = fmaxf(acc[n][1] + b1f, 0.f);
                float d2 = fmaxf(acc[n][2] + b0f, 0.f);
                float d3 = fmaxf(acc[n][3] + b1f, 0.f);
                float* p0 = nxt + (wrow + g) * XS + c;
                p0[0] = d0; p0[1] = d1;
                float* p1 = nxt + (wrow + g + 8) * XS + c;
                p1[0] = d2; p1[1] = d3;
            }
            float* tmp = cur; cur = nxt; nxt = tmp;
        } else {
            int r0v = row0 + wrow + g;
            int r1v = r0v + 8;
            bool v0 = r0v < NN, v1 = r1v < NN;
            #pragma unroll
            for (int n = 0; n < 8; n++) {
                int c = n * 8 + 2 * tg;
                float b0f = Bsm[c], b1f = Bsm[c + 1];
                float d0 = fmaxf(acc[n][0] + b0f, 0.f);
                float d1 = fmaxf(acc[n][1] + b1f, 0.f);
                float d2 = fmaxf(acc[n][2] + b0f, 0.f);
                float d3 = fmaxf(acc[n][3] + b1f, 0.f);
                if (v0) *(float2*)(g_y + (size_t)r0v * HID + c) = make_float2(d0, d1);
                if (v1) *(float2*)(g_y + (size_t)r1v * HID + c) = make_float2(d2, d3);
                float s0 = (v0 ? d0 : 0.f) + (v1 ? d2 : 0.f);
                float s1 = (v0 ? d1 : 0.f) + (v1 ? d3 : 0.f);
                float q0 = (v0 ? d0 * d0 : 0.f) + (v1 ? d2 * d2 : 0.f);
                float q1 = (v0 ? d1 * d1 : 0.f) + (v1 ? d3 * d3 : 0.f);
                #pragma unroll
                for (int off = 4; off < 32; off <<= 1) {
                    s0 += __shfl_xor_sync(0xffffffffu, s0, off);
                    s1 += __shfl_xor_sync(0xffffffffu, s1, off);
                    q0 += __shfl_xor_sync(0xffffffffu, q0, off);
                    q1 += __shfl_xor_sync(0xffffffffu, q1, off);
                }
                if (g == 0) {
                    atomicAdd(&bstat[c], s0);
                    atomicAdd(&bstat[c + 1], s1);
                    atomicAdd(&bstat[HID + c], q0);
                    atomicAdd(&bstat[HID + c + 1], q1);
                }
            }
        }
    }
    __syncthreads();
    if (t < 2 * HID) atomicAdd(&g_stats[l * 2 * HID + t], bstat[t]);
}

// BatchNorm apply + per-graph pooling (graph_ids sorted -> run-length flush)
__global__ void k_bnpool(const int* __restrict__ graph_ids,
                         const float* __restrict__ gamma,
                         const float* __restrict__ beta, int l) {
    __shared__ int gid[64];
    int c = threadIdx.x; // 64 threads, one per channel
    int r0 = blockIdx.x * 64;
    int nr = NN - r0; if (nr > 64) nr = 64;
    if (c < nr) gid[c] = graph_ids[r0 + c];
    __syncthreads();

    float sum = g_stats[l * 2 * HID + c];
    float sq = g_stats[l * 2 * HID + HID + c];
    const float invN = 1.0f / (float)NN;
    float mean = sum * invN;
    float var = sq * invN - mean * mean;
    float inv = rsqrtf(var + 1e-5f);
    float sc = __ldg(&gamma[l * HID + c]) * inv;
    float sh = __ldg(&beta[l * HID + c]) - mean * sc;

    float run = 0.f;
    int gcur = gid[0];
    for (int r = 0; r < nr; r++) {
        int gg = gid[r];
        if (gg != gcur) {
            atomicAdd(&g_pooled[(size_t)gcur * (3 * HID) + l * HID + c], run);
            run = 0.f;
            gcur = gg;
        }
        float v = g_y[(size_t)(r0 + r) * HID + c] * sc + sh;
        g_h[(size_t)(r0 + r) * HID + c] = v;
        run += v;
    }
    atomicAdd(&g_pooled[(size_t)gcur * (3 * HID) + l * HID + c], run);
}

// out[g] = pooled[g] @ W_out + b_out
__global__ void k_out(const float* __restrict__ Wo,
                      const float* __restrict__ bo,
                      float* __restrict__ out) {
    __shared__ float p[3 * HID];
    int gr = blockIdx.x;
    int t = threadIdx.x;
    for (int i = t; i < 3 * HID; i += blockDim.x)
        p[i] = g_pooled[(size_t)gr * (3 * HID) + i];
    __syncthreads();
    if (t < NCLS) {
        float a = __ldg(&bo[t]);
        #pragma unroll 8
        for (int k = 0; k < 3 * HID; k++) a += p[k] * Wo[(size_t)k * NCLS + t];
        out[(size_t)gr * NCLS + t] = a;
    }
}

// ---------------- launch ----------------
extern "C" void kernel_launch(void* const* d_in, const int* in_sizes, int n_in,
                              void* d_out, int out_size) {
    const int* node_ids = (const int*)d_in[0];
    const int* edge_src = (const int*)d_in[1];
    const int* edge_dst = (const int*)d_in[2];
    const int* graph_ids = (const int*)d_in[3];
    const float* emb = (const float*)d_in[4];
    const float* Ws = (const float*)d_in[5];
    const float* bs = (const float*)d_in[6];
    const float* gamma = (const float*)d_in[7];
    const float* beta = (const float*)d_in[8];
    const float* eps = (const float*)d_in[9];
    const float* Wo = (const float*)d_in[10];
    const float* bo = (const float*)d_in[11];
    float* out = (float*)d_out;

    cudaFuncSetAttribute(k_mlp, cudaFuncAttributeMaxDynamicSharedMemorySize,
                         MLP_SMEM);

    k_zero<<<256, 256>>>();
    k_gather<<<(NN * 16 + 255) / 256, 256>>>(node_ids, emb);

    for (int l = 0; l < 3; l++) {
        k_init<<<(NN * 16 + 255) / 256, 256>>>(eps, l);
        k_edge<<<(NE * 16 + 255) / 256, 256>>>(edge_src, edge_dst);
        k_mlp<<<(NN + MROWS - 1) / MROWS, 256, MLP_SMEM>>>(Ws, bs, l);
        k_bnpool<<<(NN + 63) / 64, 64>>>(graph_ids, gamma, beta, l);
    }

    k_out<<<NG, 128>>>(Wo, bo, out);
}